// round 15
// baseline (speedup 1.0000x reference)
#include <cuda_runtime.h>
#include <cstdint>

#define Bn 256
#define Sn 196
#define Dn 2048
#define Hn 512
#define KSPLIT 16
#define KCHUNK (Dn / KSPLIT)   // 128
#define BKT 32                 // k-chunk per smem stage (GEMM)
#define ASTRIDE 36             // smem row stride (floats): 32 + 4

// Scratch (no cudaMalloc allowed)
__device__ __align__(16) float g_atth_part[KSPLIT * Bn * Hn];  // 8 MB partials
__device__ float g_scores[Bn * Sn];

// Hardware tanh approximation (MUFU.TANH, 1 instr; validated rel_err 2.6e-6)
__device__ __forceinline__ float htanh(float x) {
    float y;
    asm("tanh.approx.f32 %0, %1;" : "=f"(y) : "f"(x));
    return y;
}

// fp32 -> tf32 bits (round-to-nearest on 10-bit mantissa, low bits zero)
__device__ __forceinline__ uint32_t tf32_of(float x) {
    uint32_t u;
    asm("cvt.rna.tf32.f32 %0, %1;" : "=r"(u) : "f"(x));
    return u;
}

// D += A*B for one m16n8k8 tf32 atom
__device__ __forceinline__ void mma_tf32(float* c, const uint32_t* a, const uint32_t* b) {
    asm volatile(
        "mma.sync.aligned.m16n8k8.row.col.f32.tf32.tf32.f32 "
        "{%0,%1,%2,%3}, {%4,%5,%6,%7}, {%8,%9}, {%0,%1,%2,%3};"
        : "+f"(c[0]), "+f"(c[1]), "+f"(c[2]), "+f"(c[3])
        : "r"(a[0]), "r"(a[1]), "r"(a[2]), "r"(a[3]), "r"(b[0]), "r"(b[1]));
}

// ---------------------------------------------------------------------------
// Kernel 1: split-K GEMM partials on tensor cores, 3xTF32 compensation,
// register-prefetched global loads (R7 pattern: LDG for tile i+1 issued
// BEFORE the MMA phase of tile i, so DRAM latency hides under tensor work).
//   part[z][m][n] = sum_{k in chunk z} h[m,k] * W[n,k]
// Block 128 thr (4 warps, 2x2), tile 64m x 64n, BK=32. Grid (8,4,16)=512.
// ---------------------------------------------------------------------------
__global__ __launch_bounds__(128) void k_h2att_sk(const float* __restrict__ A,
                                                  const float* __restrict__ W) {
    __shared__ __align__(16) uint32_t Ah[64 * ASTRIDE];  // [m][k] hi
    __shared__ __align__(16) uint32_t Al[64 * ASTRIDE];  // [m][k] lo
    __shared__ __align__(16) uint32_t Bh[64 * ASTRIDE];  // [n][k] hi
    __shared__ __align__(16) uint32_t Bl[64 * ASTRIDE];  // [n][k] lo

    const int tid = threadIdx.x;
    const int lane = tid & 31;
    const int warp = tid >> 5;            // 0..3
    const int g = lane >> 2;              // groupID 0..7
    const int tg = lane & 3;              // threadID_in_group 0..3
    const int wm = (warp >> 1) * 32;      // warp m-offset within tile
    const int wn = (warp & 1) * 32;       // warp n-offset within tile

    const int n0 = blockIdx.x * 64;
    const int m0 = blockIdx.y * 64;
    const int kbase = blockIdx.z * KCHUNK;

    const int fr = tid >> 1;              // fill row 0..63
    const int fk = (tid & 1) * 16;        // fill k-segment 0 or 16

    const float* arow = &A[(m0 + fr) * Dn + kbase + fk];
    const float* brow = &W[(n0 + fr) * Dn + kbase + fk];

    float c[2][4][4] = {};                // [m-atom][n-atom][frag]

    // prologue: LDG tile 0 into registers
    float4 areg[4], breg[4];
#pragma unroll
    for (int j = 0; j < 4; j++) {
        areg[j] = *(const float4*)(arow + j * 4);
        breg[j] = *(const float4*)(brow + j * 4);
    }

    for (int kt = 0; kt < BKT * 4; kt += BKT) {   // KCHUNK == 4*BKT
        __syncthreads();                  // previous MMA phase done; smem reusable
        // ---- cvt + STS of the registers loaded last iteration ----
#pragma unroll
        for (int j = 0; j < 4; j++) {
            const int kk = fk + j * 4;
            float4 a4 = areg[j];
            float4 b4 = breg[j];
            uint4 ahi, alo, bhi, blo;
            ahi.x = tf32_of(a4.x); alo.x = tf32_of(a4.x - __uint_as_float(ahi.x));
            ahi.y = tf32_of(a4.y); alo.y = tf32_of(a4.y - __uint_as_float(ahi.y));
            ahi.z = tf32_of(a4.z); alo.z = tf32_of(a4.z - __uint_as_float(ahi.z));
            ahi.w = tf32_of(a4.w); alo.w = tf32_of(a4.w - __uint_as_float(ahi.w));
            bhi.x = tf32_of(b4.x); blo.x = tf32_of(b4.x - __uint_as_float(bhi.x));
            bhi.y = tf32_of(b4.y); blo.y = tf32_of(b4.y - __uint_as_float(bhi.y));
            bhi.z = tf32_of(b4.z); blo.z = tf32_of(b4.z - __uint_as_float(bhi.z));
            bhi.w = tf32_of(b4.w); blo.w = tf32_of(b4.w - __uint_as_float(bhi.w));
            *(uint4*)&Ah[fr * ASTRIDE + kk] = ahi;
            *(uint4*)&Al[fr * ASTRIDE + kk] = alo;
            *(uint4*)&Bh[fr * ASTRIDE + kk] = bhi;
            *(uint4*)&Bl[fr * ASTRIDE + kk] = blo;
        }
        __syncthreads();

        // ---- prefetch next tile: LDG in flight through the MMA phase ----
        if (kt + BKT < KCHUNK) {
#pragma unroll
            for (int j = 0; j < 4; j++) {
                areg[j] = *(const float4*)(arow + kt + BKT + j * 4);
                breg[j] = *(const float4*)(brow + kt + BKT + j * 4);
            }
        }

        // ---- 4 k8-steps of mma ----
#pragma unroll
        for (int ks = 0; ks < 4; ks++) {
            const int kk = ks * 8;
            uint32_t ah[2][4], al[2][4], bh[4][2], bl[4][2];
#pragma unroll
            for (int am = 0; am < 2; am++) {
                const int r0 = (wm + am * 16 + g) * ASTRIDE + kk + tg;
                const int r8 = r0 + 8 * ASTRIDE;
                ah[am][0] = Ah[r0];     ah[am][1] = Ah[r8];
                ah[am][2] = Ah[r0 + 4]; ah[am][3] = Ah[r8 + 4];
                al[am][0] = Al[r0];     al[am][1] = Al[r8];
                al[am][2] = Al[r0 + 4]; al[am][3] = Al[r8 + 4];
            }
#pragma unroll
            for (int j = 0; j < 4; j++) {
                const int rb = (wn + j * 8 + g) * ASTRIDE + kk + tg;
                bh[j][0] = Bh[rb]; bh[j][1] = Bh[rb + 4];
                bl[j][0] = Bl[rb]; bl[j][1] = Bl[rb + 4];
            }
#pragma unroll
            for (int am = 0; am < 2; am++)
#pragma unroll
                for (int j = 0; j < 4; j++) {
                    mma_tf32(c[am][j], ah[am], bh[j]);   // hi*hi
                    mma_tf32(c[am][j], al[am], bh[j]);   // lo*hi
                    mma_tf32(c[am][j], ah[am], bl[j]);   // hi*lo
                }
        }
    }

    // ---- epilogue: c-fragment scatter to partials ----
    float* dst = g_atth_part + (size_t)blockIdx.z * (Bn * Hn);
#pragma unroll
    for (int am = 0; am < 2; am++) {
#pragma unroll
        for (int j = 0; j < 4; j++) {
            const int row = m0 + wm + am * 16 + g;
            const int col = n0 + wn + j * 8 + 2 * tg;
            *(float2*)&dst[row * Hn + col] =
                make_float2(c[am][j][0], c[am][j][1]);
            *(float2*)&dst[(row + 8) * Hn + col] =
                make_float2(c[am][j][2], c[am][j][3]);
        }
    }
}

// ---------------------------------------------------------------------------
// Kernel 2: raw scores, 2-slot ILP + hardware tanh (proven body).
// Grid (B, 7), 448 threads. att_h assembled from 16 partials + bias (L2).
// ---------------------------------------------------------------------------
__global__ __launch_bounds__(448) void k_scores(const float* __restrict__ p_att,
                                                const float* __restrict__ w_alpha,
                                                const float* __restrict__ bias,
                                                const float* __restrict__ b_alpha) {
    __shared__ float ah[Hn];
    __shared__ float wa[Hn];

    const int b = blockIdx.x;
    const int sgrp = blockIdx.y;          // 0..6, 28 slots each
    const int tid = threadIdx.x;
    const int lane = tid & 31;
    const int warp = tid >> 5;            // 0..13

    for (int h = tid; h < Hn; h += 448) {
        float acc = bias[h];
#pragma unroll
        for (int z = 0; z < KSPLIT; z++)
            acc += g_atth_part[z * (Bn * Hn) + b * Hn + h];
        ah[h] = acc;
        wa[h] = w_alpha[h];
    }
    __syncthreads();

    const float balpha = b_alpha[0];
    const float4* a4p = (const float4*)ah;
    const float4* w4p = (const float4*)wa;

    const int s0 = sgrp * 28 + warp * 2;
    const float4* pr0 = (const float4*)(p_att + ((long)b * Sn + s0) * Hn);
    const float4* pr1 = (const float4*)(p_att + ((long)b * Sn + s0 + 1) * Hn);

    float l0 = 0.0f, l1 = 0.0f;
#pragma unroll
    for (int i = 0; i < 4; i++) {
        const int h4 = i * 32 + lane;
        float4 pa = pr0[h4];
        float4 pb = pr1[h4];
        float4 a4 = a4p[h4];
        float4 w4 = w4p[h4];
        l0 += htanh(pa.x + a4.x) * w4.x;
        l1 += htanh(pb.x + a4.x) * w4.x;
        l0 += htanh(pa.y + a4.y) * w4.y;
        l1 += htanh(pb.y + a4.y) * w4.y;
        l0 += htanh(pa.z + a4.z) * w4.z;
        l1 += htanh(pb.z + a4.z) * w4.z;
        l0 += htanh(pa.w + a4.w) * w4.w;
        l1 += htanh(pb.w + a4.w) * w4.w;
    }
#pragma unroll
    for (int o = 16; o > 0; o >>= 1) {
        l0 += __shfl_xor_sync(0xffffffffu, l0, o);
        l1 += __shfl_xor_sync(0xffffffffu, l1, o);
    }
    if (lane == 0) {
        g_scores[b * Sn + s0]     = l0 + balpha;
        g_scores[b * Sn + s0 + 1] = l1 + balpha;
    }
}

// ---------------------------------------------------------------------------
// Kernel 3: fused masked-softmax prologue + weighted sum.
// Grid (4, B) x 128 threads. w_i = e_i*m_i / sum_j(e_j*m_j).
// ---------------------------------------------------------------------------
__global__ __launch_bounds__(128) void k_attres(const float* __restrict__ att_feats,
                                                const float* __restrict__ mask,
                                                float* __restrict__ out) {
    __shared__ float w[Sn];
    __shared__ float redm[4];
    __shared__ float reds[4];

    const int b = blockIdx.y;
    const int tid = threadIdx.x;
    const int lane = tid & 31;
    const int warp = tid >> 5;

    const float v0 = g_scores[b * Sn + tid];
    const float v1 = (tid + 128 < Sn) ? g_scores[b * Sn + tid + 128] : -3.402823e38f;

    float m = fmaxf(v0, v1);
#pragma unroll
    for (int o = 16; o > 0; o >>= 1)
        m = fmaxf(m, __shfl_xor_sync(0xffffffffu, m, o));
    if (lane == 0) redm[warp] = m;
    __syncthreads();
    m = fmaxf(fmaxf(redm[0], redm[1]), fmaxf(redm[2], redm[3]));

    float e0 = __expf(v0 - m) * mask[b * Sn + tid];
    float e1 = (tid + 128 < Sn) ? __expf(v1 - m) * mask[b * Sn + tid + 128] : 0.0f;
    float s = e0 + e1;
#pragma unroll
    for (int o = 16; o > 0; o >>= 1)
        s += __shfl_xor_sync(0xffffffffu, s, o);
    if (lane == 0) reds[warp] = s;
    __syncthreads();
    const float inv = 1.0f / (reds[0] + reds[1] + reds[2] + reds[3]);

    w[tid] = e0 * inv;
    if (tid + 128 < Sn) w[tid + 128] = e1 * inv;
    __syncthreads();

    const int d0 = blockIdx.x * 512 + tid * 4;
    const float* base = att_feats + (long)b * Sn * Dn + d0;

    float4 acc = make_float4(0.f, 0.f, 0.f, 0.f);
#pragma unroll 8
    for (int s2 = 0; s2 < Sn; s2++) {
        float4 f = *(const float4*)(base + (long)s2 * Dn);
        float ws = w[s2];
        acc.x += ws * f.x;
        acc.y += ws * f.y;
        acc.z += ws * f.z;
        acc.w += ws * f.w;
    }
    *(float4*)(out + (long)b * Dn + d0) = acc;
}

// ---------------------------------------------------------------------------

extern "C" void kernel_launch(void* const* d_in, const int* in_sizes, int n_in,
                              void* d_out, int out_size) {
    const float* h         = (const float*)d_in[0];  // [B, D]
    const float* att_feats = (const float*)d_in[1];  // [B, S, D]
    const float* p_att     = (const float*)d_in[2];  // [B, S, H]
    const float* mask      = (const float*)d_in[3];  // [B, S]
    const float* W_h2att   = (const float*)d_in[4];  // [H, D]
    const float* b_h2att   = (const float*)d_in[5];  // [H]
    const float* w_alpha   = (const float*)d_in[6];  // [H]
    const float* b_alpha   = (const float*)d_in[7];  // scalar
    float* out = (float*)d_out;                      // [B, D]

    (void)in_sizes; (void)n_in; (void)out_size;

    dim3 g1(Hn / 64, Bn / 64, KSPLIT);  // (8, 4, 16) = 512 blocks
    k_h2att_sk<<<g1, 128>>>(h, W_h2att);

    dim3 g2(Bn, 7);                     // 1792 blocks, 448 thr
    k_scores<<<g2, 448>>>(p_att, w_alpha, b_h2att, b_alpha);

    dim3 g3(4, Bn);                     // 1024 blocks
    k_attres<<<g3, 128>>>(att_feats, mask, out);
}

// round 16
// speedup vs baseline: 1.0221x; 1.0221x over previous
#include <cuda_runtime.h>
#include <cstdint>

#define Bn 256
#define Sn 196
#define Dn 2048
#define Hn 512
#define KSPLIT 16
#define KCHUNK (Dn / KSPLIT)   // 128
#define BKT 32                 // k-chunk per smem stage (GEMM)
#define ASTRIDE 36             // smem row stride (floats): 32 + 4

// Scratch (no cudaMalloc allowed)
__device__ __align__(16) float g_atth_part[KSPLIT * Bn * Hn];  // 8 MB partials
__device__ float g_scores[Bn * Sn];

// Hardware tanh approximation (MUFU.TANH, 1 instr; validated rel_err 2.6e-6)
__device__ __forceinline__ float htanh(float x) {
    float y;
    asm("tanh.approx.f32 %0, %1;" : "=f"(y) : "f"(x));
    return y;
}

// fp32 -> tf32 bits (round-to-nearest on 10-bit mantissa, low bits zero)
__device__ __forceinline__ uint32_t tf32_of(float x) {
    uint32_t u;
    asm("cvt.rna.tf32.f32 %0, %1;" : "=r"(u) : "f"(x));
    return u;
}

// D += A*B for one m16n8k8 tf32 atom
__device__ __forceinline__ void mma_tf32(float* c, const uint32_t* a, const uint32_t* b) {
    asm volatile(
        "mma.sync.aligned.m16n8k8.row.col.f32.tf32.tf32.f32 "
        "{%0,%1,%2,%3}, {%4,%5,%6,%7}, {%8,%9}, {%0,%1,%2,%3};"
        : "+f"(c[0]), "+f"(c[1]), "+f"(c[2]), "+f"(c[3])
        : "r"(a[0]), "r"(a[1]), "r"(a[2]), "r"(a[3]), "r"(b[0]), "r"(b[1]));
}

// ---------------------------------------------------------------------------
// Kernel 1: split-K GEMM partials on tensor cores, 3xTF32 compensation.
// 256 threads = 8 warps (4m x 2n); each warp owns 16m x 32n -> HALF the
// per-warp fragment/MMA work of the R13 shape, DOUBLE the resident warps
// (R13/R15 showed occ ~18% was the binding constraint, not the pipes).
//   part[z][m][n] = sum_{k in chunk z} h[m,k] * W[n,k]
// Tile 64m x 64n, BK=32. Grid (8,4,16) = 512 blocks.
// ---------------------------------------------------------------------------
__global__ __launch_bounds__(256) void k_h2att_sk(const float* __restrict__ A,
                                                  const float* __restrict__ W) {
    __shared__ __align__(16) uint32_t Ah[64 * ASTRIDE];  // [m][k] hi
    __shared__ __align__(16) uint32_t Al[64 * ASTRIDE];  // [m][k] lo
    __shared__ __align__(16) uint32_t Bh[64 * ASTRIDE];  // [n][k] hi
    __shared__ __align__(16) uint32_t Bl[64 * ASTRIDE];  // [n][k] lo

    const int tid = threadIdx.x;
    const int lane = tid & 31;
    const int warp = tid >> 5;            // 0..7
    const int g = lane >> 2;              // groupID 0..7
    const int tg = lane & 3;              // threadID_in_group 0..3
    const int wm = (warp >> 1) * 16;      // warp m-offset (0,16,32,48)
    const int wn = (warp & 1) * 32;       // warp n-offset (0,32)

    const int n0 = blockIdx.x * 64;
    const int m0 = blockIdx.y * 64;
    const int kbase = blockIdx.z * KCHUNK;

    const int fr = tid >> 2;              // fill row 0..63
    const int fk = (tid & 3) * 8;         // fill k-segment 0,8,16,24

    const float* arow = &A[(m0 + fr) * Dn + kbase + fk];
    const float* brow = &W[(n0 + fr) * Dn + kbase + fk];

    float c[4][4] = {};                   // [n-atom][frag], single m-atom

    // prologue: LDG tile 0 into registers (2 float4 each for A and B)
    float4 areg[2], breg[2];
#pragma unroll
    for (int j = 0; j < 2; j++) {
        areg[j] = *(const float4*)(arow + j * 4);
        breg[j] = *(const float4*)(brow + j * 4);
    }

    for (int kt = 0; kt < BKT * 4; kt += BKT) {   // KCHUNK == 4*BKT
        __syncthreads();                  // previous MMA phase done; smem reusable
        // ---- cvt + STS of the registers loaded last iteration ----
#pragma unroll
        for (int j = 0; j < 2; j++) {
            const int kk = fk + j * 4;
            float4 a4 = areg[j];
            float4 b4 = breg[j];
            uint4 ahi, alo, bhi, blo;
            ahi.x = tf32_of(a4.x); alo.x = tf32_of(a4.x - __uint_as_float(ahi.x));
            ahi.y = tf32_of(a4.y); alo.y = tf32_of(a4.y - __uint_as_float(ahi.y));
            ahi.z = tf32_of(a4.z); alo.z = tf32_of(a4.z - __uint_as_float(ahi.z));
            ahi.w = tf32_of(a4.w); alo.w = tf32_of(a4.w - __uint_as_float(ahi.w));
            bhi.x = tf32_of(b4.x); blo.x = tf32_of(b4.x - __uint_as_float(bhi.x));
            bhi.y = tf32_of(b4.y); blo.y = tf32_of(b4.y - __uint_as_float(bhi.y));
            bhi.z = tf32_of(b4.z); blo.z = tf32_of(b4.z - __uint_as_float(bhi.z));
            bhi.w = tf32_of(b4.w); blo.w = tf32_of(b4.w - __uint_as_float(bhi.w));
            *(uint4*)&Ah[fr * ASTRIDE + kk] = ahi;
            *(uint4*)&Al[fr * ASTRIDE + kk] = alo;
            *(uint4*)&Bh[fr * ASTRIDE + kk] = bhi;
            *(uint4*)&Bl[fr * ASTRIDE + kk] = blo;
        }
        __syncthreads();

        // ---- prefetch next tile: LDG in flight through the MMA phase ----
        if (kt + BKT < KCHUNK) {
#pragma unroll
            for (int j = 0; j < 2; j++) {
                areg[j] = *(const float4*)(arow + kt + BKT + j * 4);
                breg[j] = *(const float4*)(brow + kt + BKT + j * 4);
            }
        }

        // ---- 4 k8-steps of mma ----
#pragma unroll
        for (int ks = 0; ks < 4; ks++) {
            const int kk = ks * 8;
            uint32_t ah[4], al[4], bh[4][2], bl[4][2];
            {
                const int r0 = (wm + g) * ASTRIDE + kk + tg;
                const int r8 = r0 + 8 * ASTRIDE;
                ah[0] = Ah[r0];     ah[1] = Ah[r8];
                ah[2] = Ah[r0 + 4]; ah[3] = Ah[r8 + 4];
                al[0] = Al[r0];     al[1] = Al[r8];
                al[2] = Al[r0 + 4]; al[3] = Al[r8 + 4];
            }
#pragma unroll
            for (int j = 0; j < 4; j++) {
                const int rb = (wn + j * 8 + g) * ASTRIDE + kk + tg;
                bh[j][0] = Bh[rb]; bh[j][1] = Bh[rb + 4];
                bl[j][0] = Bl[rb]; bl[j][1] = Bl[rb + 4];
            }
#pragma unroll
            for (int j = 0; j < 4; j++) {
                mma_tf32(c[j], ah, bh[j]);   // hi*hi
                mma_tf32(c[j], al, bh[j]);   // lo*hi
                mma_tf32(c[j], ah, bl[j]);   // hi*lo
            }
        }
    }

    // ---- epilogue: c-fragment scatter to partials ----
    float* dst = g_atth_part + (size_t)blockIdx.z * (Bn * Hn);
#pragma unroll
    for (int j = 0; j < 4; j++) {
        const int row = m0 + wm + g;
        const int col = n0 + wn + j * 8 + 2 * tg;
        *(float2*)&dst[row * Hn + col]       = make_float2(c[j][0], c[j][1]);
        *(float2*)&dst[(row + 8) * Hn + col] = make_float2(c[j][2], c[j][3]);
    }
}

// ---------------------------------------------------------------------------
// Kernel 2: raw scores, 2-slot ILP + hardware tanh (proven body).
// Grid (B, 7), 448 threads. att_h assembled from 16 partials + bias (L2).
// ---------------------------------------------------------------------------
__global__ __launch_bounds__(448) void k_scores(const float* __restrict__ p_att,
                                                const float* __restrict__ w_alpha,
                                                const float* __restrict__ bias,
                                                const float* __restrict__ b_alpha) {
    __shared__ float ah[Hn];
    __shared__ float wa[Hn];

    const int b = blockIdx.x;
    const int sgrp = blockIdx.y;          // 0..6, 28 slots each
    const int tid = threadIdx.x;
    const int lane = tid & 31;
    const int warp = tid >> 5;            // 0..13

    for (int h = tid; h < Hn; h += 448) {
        float acc = bias[h];
#pragma unroll
        for (int z = 0; z < KSPLIT; z++)
            acc += g_atth_part[z * (Bn * Hn) + b * Hn + h];
        ah[h] = acc;
        wa[h] = w_alpha[h];
    }
    __syncthreads();

    const float balpha = b_alpha[0];
    const float4* a4p = (const float4*)ah;
    const float4* w4p = (const float4*)wa;

    const int s0 = sgrp * 28 + warp * 2;
    const float4* pr0 = (const float4*)(p_att + ((long)b * Sn + s0) * Hn);
    const float4* pr1 = (const float4*)(p_att + ((long)b * Sn + s0 + 1) * Hn);

    float l0 = 0.0f, l1 = 0.0f;
#pragma unroll
    for (int i = 0; i < 4; i++) {
        const int h4 = i * 32 + lane;
        float4 pa = pr0[h4];
        float4 pb = pr1[h4];
        float4 a4 = a4p[h4];
        float4 w4 = w4p[h4];
        l0 += htanh(pa.x + a4.x) * w4.x;
        l1 += htanh(pb.x + a4.x) * w4.x;
        l0 += htanh(pa.y + a4.y) * w4.y;
        l1 += htanh(pb.y + a4.y) * w4.y;
        l0 += htanh(pa.z + a4.z) * w4.z;
        l1 += htanh(pb.z + a4.z) * w4.z;
        l0 += htanh(pa.w + a4.w) * w4.w;
        l1 += htanh(pb.w + a4.w) * w4.w;
    }
#pragma unroll
    for (int o = 16; o > 0; o >>= 1) {
        l0 += __shfl_xor_sync(0xffffffffu, l0, o);
        l1 += __shfl_xor_sync(0xffffffffu, l1, o);
    }
    if (lane == 0) {
        g_scores[b * Sn + s0]     = l0 + balpha;
        g_scores[b * Sn + s0 + 1] = l1 + balpha;
    }
}

// ---------------------------------------------------------------------------
// Kernel 3: fused masked-softmax prologue + weighted sum.
// Grid (4, B) x 128 threads. w_i = e_i*m_i / sum_j(e_j*m_j).
// ---------------------------------------------------------------------------
__global__ __launch_bounds__(128) void k_attres(const float* __restrict__ att_feats,
                                                const float* __restrict__ mask,
                                                float* __restrict__ out) {
    __shared__ float w[Sn];
    __shared__ float redm[4];
    __shared__ float reds[4];

    const int b = blockIdx.y;
    const int tid = threadIdx.x;
    const int lane = tid & 31;
    const int warp = tid >> 5;

    const float v0 = g_scores[b * Sn + tid];
    const float v1 = (tid + 128 < Sn) ? g_scores[b * Sn + tid + 128] : -3.402823e38f;

    float m = fmaxf(v0, v1);
#pragma unroll
    for (int o = 16; o > 0; o >>= 1)
        m = fmaxf(m, __shfl_xor_sync(0xffffffffu, m, o));
    if (lane == 0) redm[warp] = m;
    __syncthreads();
    m = fmaxf(fmaxf(redm[0], redm[1]), fmaxf(redm[2], redm[3]));

    float e0 = __expf(v0 - m) * mask[b * Sn + tid];
    float e1 = (tid + 128 < Sn) ? __expf(v1 - m) * mask[b * Sn + tid + 128] : 0.0f;
    float s = e0 + e1;
#pragma unroll
    for (int o = 16; o > 0; o >>= 1)
        s += __shfl_xor_sync(0xffffffffu, s, o);
    if (lane == 0) reds[warp] = s;
    __syncthreads();
    const float inv = 1.0f / (reds[0] + reds[1] + reds[2] + reds[3]);

    w[tid] = e0 * inv;
    if (tid + 128 < Sn) w[tid + 128] = e1 * inv;
    __syncthreads();

    const int d0 = blockIdx.x * 512 + tid * 4;
    const float* base = att_feats + (long)b * Sn * Dn + d0;

    float4 acc = make_float4(0.f, 0.f, 0.f, 0.f);
#pragma unroll 8
    for (int s2 = 0; s2 < Sn; s2++) {
        float4 f = *(const float4*)(base + (long)s2 * Dn);
        float ws = w[s2];
        acc.x += ws * f.x;
        acc.y += ws * f.y;
        acc.z += ws * f.z;
        acc.w += ws * f.w;
    }
    *(float4*)(out + (long)b * Dn + d0) = acc;
}

// ---------------------------------------------------------------------------

extern "C" void kernel_launch(void* const* d_in, const int* in_sizes, int n_in,
                              void* d_out, int out_size) {
    const float* h         = (const float*)d_in[0];  // [B, D]
    const float* att_feats = (const float*)d_in[1];  // [B, S, D]
    const float* p_att     = (const float*)d_in[2];  // [B, S, H]
    const float* mask      = (const float*)d_in[3];  // [B, S]
    const float* W_h2att   = (const float*)d_in[4];  // [H, D]
    const float* b_h2att   = (const float*)d_in[5];  // [H]
    const float* w_alpha   = (const float*)d_in[6];  // [H]
    const float* b_alpha   = (const float*)d_in[7];  // scalar
    float* out = (float*)d_out;                      // [B, D]

    (void)in_sizes; (void)n_in; (void)out_size;

    dim3 g1(Hn / 64, Bn / 64, KSPLIT);  // (8, 4, 16) = 512 blocks
    k_h2att_sk<<<g1, 256>>>(h, W_h2att);

    dim3 g2(Bn, 7);                     // 1792 blocks, 448 thr
    k_scores<<<g2, 448>>>(p_att, w_alpha, b_h2att, b_alpha);

    dim3 g3(4, Bn);                     // 1024 blocks
    k_attres<<<g3, 128>>>(att_feats, mask, out);
}